// round 1
// baseline (speedup 1.0000x reference)
#include <cuda_runtime.h>

#define Bq 8192
#define Tq 2048
#define DEG 12
#define SFIT 1.05
#define PI_D 3.14159265358979323846

// ---------------- packed f32x2 helpers (sm_103a) ----------------
__device__ __forceinline__ float2 ffma2(float2 a, float2 b, float2 c) {
    float2 d;
    asm("{\n\t.reg .b64 ra,rb,rc,rd;\n\t"
        "mov.b64 ra,{%2,%3};\n\t"
        "mov.b64 rb,{%4,%5};\n\t"
        "mov.b64 rc,{%6,%7};\n\t"
        "fma.rn.f32x2 rd,ra,rb,rc;\n\t"
        "mov.b64 {%0,%1},rd;\n\t}"
        : "=f"(d.x), "=f"(d.y)
        : "f"(a.x), "f"(a.y), "f"(b.x), "f"(b.y), "f"(c.x), "f"(c.y));
    return d;
}
__device__ __forceinline__ float2 fmul2(float2 a, float2 b) {
    float2 d;
    asm("{\n\t.reg .b64 ra,rb,rd;\n\t"
        "mov.b64 ra,{%2,%3};\n\t"
        "mov.b64 rb,{%4,%5};\n\t"
        "mul.rn.f32x2 rd,ra,rb;\n\t"
        "mov.b64 {%0,%1},rd;\n\t}"
        : "=f"(d.x), "=f"(d.y)
        : "f"(a.x), "f"(a.y), "f"(b.x), "f"(b.y));
    return d;
}
__device__ __forceinline__ float2 fadd2(float2 a, float2 b) {
    float2 d;
    asm("{\n\t.reg .b64 ra,rb,rd;\n\t"
        "mov.b64 ra,{%2,%3};\n\t"
        "mov.b64 rb,{%4,%5};\n\t"
        "add.rn.f32x2 rd,ra,rb;\n\t"
        "mov.b64 {%0,%1},rd;\n\t}"
        : "=f"(d.x), "=f"(d.y)
        : "f"(a.x), "f"(a.y), "f"(b.x), "f"(b.y));
    return d;
}
__device__ __forceinline__ float tanhap(float x) {
    float y;
    asm("tanh.approx.f32 %0, %1;" : "=f"(y) : "f"(x));
    return y;
}

// ---------------- device-global precomputed constants ----------------
struct Consts {
    float2 wih_r, wih_z, wih_n;       // input weights (r,z folded by 0.5)
    float2 b_r, b_z, b_nx, b_nh;      // biases (r,z: 0.5*(b_ih+b_hh))
    float2 wr0, wr1, wz0, wz1, wn0, wn1;  // recurrent weights, cols 0/1, comps packed
};
__device__ Consts g_c;
__device__ float2 g_poly[DEG + 1];    // monomial coeffs (alphaPoly, betaPoly), low->high

// ---------------- setup: fold weights + fit output polynomials on device ----------------
__global__ void setup_kernel(const float* __restrict__ wih, const float* __restrict__ whh,
                             const float* __restrict__ bih, const float* __restrict__ bhh) {
    if (threadIdx.x != 0 || blockIdx.x != 0) return;
    Consts c;
    // gate row order: r = rows 0,1 ; z = rows 2,3 ; n = rows 4,5. whh row-major (6x2).
    c.wih_r = make_float2(0.5f * wih[0], 0.5f * wih[1]);
    c.wih_z = make_float2(0.5f * wih[2], 0.5f * wih[3]);
    c.wih_n = make_float2(wih[4], wih[5]);
    c.b_r  = make_float2(0.5f * (bih[0] + bhh[0]), 0.5f * (bih[1] + bhh[1]));
    c.b_z  = make_float2(0.5f * (bih[2] + bhh[2]), 0.5f * (bih[3] + bhh[3]));
    c.b_nx = make_float2(bih[4], bih[5]);
    c.b_nh = make_float2(bhh[4], bhh[5]);
    c.wr0 = make_float2(0.5f * whh[0 * 2 + 0], 0.5f * whh[1 * 2 + 0]);
    c.wr1 = make_float2(0.5f * whh[0 * 2 + 1], 0.5f * whh[1 * 2 + 1]);
    c.wz0 = make_float2(0.5f * whh[2 * 2 + 0], 0.5f * whh[3 * 2 + 0]);
    c.wz1 = make_float2(0.5f * whh[2 * 2 + 1], 0.5f * whh[3 * 2 + 1]);
    c.wn0 = make_float2(whh[4 * 2 + 0], whh[5 * 2 + 0]);
    c.wn1 = make_float2(whh[4 * 2 + 1], whh[5 * 2 + 1]);
    g_c = c;

    // Chebyshev fit of fA(x)=2.5*exp(tanh(x)), fB(x)=4*sigmoid(tanh(x)) on [-SFIT,SFIT]
    const int N = 512;
    double cA[DEG + 1], cB[DEG + 1];
    for (int k = 0; k <= DEG; k++) { cA[k] = 0.0; cB[k] = 0.0; }
    for (int j = 0; j < N; j++) {
        double th = PI_D * (j + 0.5) / N;
        double u = cos(th);
        double x = SFIT * u;
        double t = tanh(x);
        double fa = 2.5 * exp(t);
        double fb = 4.0 / (1.0 + exp(-t));
        for (int k = 0; k <= DEG; k++) {
            double w = cos(k * th) * (2.0 / N);
            cA[k] += fa * w;
            cB[k] += fb * w;
        }
    }
    cA[0] *= 0.5; cB[0] *= 0.5;

    // Chebyshev -> monomial (in u), then rescale u = x/SFIT
    double mA[DEG + 1], mB[DEG + 1], tp[DEG + 1], tc[DEG + 1], tn[DEG + 1];
    for (int i = 0; i <= DEG; i++) { mA[i] = mB[i] = tp[i] = tc[i] = tn[i] = 0.0; }
    tp[0] = 1.0;       // T0
    tc[1] = 1.0;       // T1
    for (int i = 0; i <= DEG; i++) { mA[i] += cA[0] * tp[i]; mB[i] += cB[0] * tp[i]; }
    for (int i = 0; i <= DEG; i++) { mA[i] += cA[1] * tc[i]; mB[i] += cB[1] * tc[i]; }
    for (int k = 2; k <= DEG; k++) {
        for (int i = 0; i <= DEG; i++) tn[i] = -tp[i];
        for (int i = DEG; i >= 1; i--) tn[i] += 2.0 * tc[i - 1];
        for (int i = 0; i <= DEG; i++) {
            mA[i] += cA[k] * tn[i];
            mB[i] += cB[k] * tn[i];
            tp[i] = tc[i];
            tc[i] = tn[i];
        }
    }
    double s = 1.0;
    for (int i = 0; i <= DEG; i++) {
        g_poly[i] = make_float2((float)(mA[i] / s), (float)(mB[i] / s));
        s *= SFIT;
    }
}

// ---------------- main GRU scan kernel: 1 thread = 1 batch row ----------------
__global__ void __launch_bounds__(64, 1)
gru_kernel(const float* __restrict__ x, float* __restrict__ out) {
    const int b = blockIdx.x * 64 + threadIdx.x;

    const Consts c = g_c;
    float2 P[DEG + 1];
#pragma unroll
    for (int i = 0; i <= DEG; i++) P[i] = g_poly[i];

    const float2 half2  = make_float2(0.5f, 0.5f);
    const float2 nhalf2 = make_float2(-0.5f, -0.5f);

    const float* xr = x + (size_t)b * Tq;
    float4* orow = reinterpret_cast<float4*>(out + (size_t)b * Tq * 2);

    // 3-deep float4 prefetch ring (DRAM latency ~600cy vs ~200cy/iter)
    float4 xc = *(const float4*)(xr);
    float4 x1 = *(const float4*)(xr + 4);
    float4 x2 = *(const float4*)(xr + 8);

    float2 h = make_float2(0.f, 0.f);

    for (int t0 = 0; t0 < Tq; t0 += 4) {
        int tpf = (t0 + 12 <= Tq - 4) ? (t0 + 12) : (Tq - 4);
        float4 xnext = *(const float4*)(xr + tpf);

        float2 ob[4];
#pragma unroll
        for (int s = 0; s < 4; s++) {
            float xt = (s == 0) ? xc.x : (s == 1) ? xc.y : (s == 2) ? xc.z : xc.w;
            float2 xx = make_float2(xt, xt);
            float2 h0 = make_float2(h.x, h.x);
            float2 h1 = make_float2(h.y, h.y);

            // pre-activations (0.5 folded into r,z paths for sigmoid-as-tanh)
            float2 sr = ffma2(h0, c.wr0, ffma2(h1, c.wr1, ffma2(xx, c.wih_r, c.b_r)));
            float2 sz = ffma2(h0, c.wz0, ffma2(h1, c.wz1, ffma2(xx, c.wih_z, c.b_z)));
            float2 nh = ffma2(h0, c.wn0, ffma2(h1, c.wn1, c.b_nh));
            float2 nx = ffma2(xx, c.wih_n, c.b_nx);

            float2 tr, tz;
            tr.x = tanhap(sr.x); tr.y = tanhap(sr.y);
            tz.x = tanhap(sz.x); tz.y = tanhap(sz.y);

            // n = tanh(nx + r*nh),  r = 0.5*tr + 0.5
            float2 q  = fmul2(half2, nh);       // 0.5*nh
            float2 p  = fadd2(q, nx);           // nx + 0.5*nh
            float2 na = ffma2(tr, q, p);
            float2 n;
            n.x = tanhap(na.x); n.y = tanhap(na.y);

            // h_new = n*(0.5-0.5tz) + h*(0.5+0.5tz)
            float2 zp = ffma2(tz, half2, half2);    // z
            float2 zm = ffma2(tz, nhalf2, half2);   // 1-z
            float2 hb = fmul2(h, zp);
            h = ffma2(n, zm, hb);

            // outputs: packed Horner, lane.x -> alphaPoly(h0), lane.y -> betaPoly(h1)
            float2 acc = P[DEG];
#pragma unroll
            for (int k = DEG - 1; k >= 0; k--) acc = ffma2(acc, h, P[k]);
            ob[s] = acc;
        }

        orow[(t0 >> 1) + 0] = make_float4(ob[0].x, ob[0].y, ob[1].x, ob[1].y);
        orow[(t0 >> 1) + 1] = make_float4(ob[2].x, ob[2].y, ob[3].x, ob[3].y);

        xc = x1; x1 = x2; x2 = xnext;
    }
}

extern "C" void kernel_launch(void* const* d_in, const int* in_sizes, int n_in,
                              void* d_out, int out_size) {
    const float* x   = (const float*)d_in[0];
    const float* wih = (const float*)d_in[1];
    const float* whh = (const float*)d_in[2];
    const float* bih = (const float*)d_in[3];
    const float* bhh = (const float*)d_in[4];

    setup_kernel<<<1, 32>>>(wih, whh, bih, bhh);
    gru_kernel<<<128, 64>>>(x, (float*)d_out);
}

// round 2
// speedup vs baseline: 27.3157x; 27.3157x over previous
#include <cuda_runtime.h>
#include <math.h>

#define Bq 8192
#define Tq 2048
#define DEG 10
#define SFIT 1.05
#define PI_D 3.14159265358979323846

typedef unsigned long long ull;

// ---------------- packed f32x2 helpers: b64 registers, no pack/unpack movs ----
__device__ __forceinline__ ull pk2(float lo, float hi) {
    ull r;
    asm("mov.b64 %0,{%1,%2};" : "=l"(r) : "f"(lo), "f"(hi));
    return r;
}
__device__ __forceinline__ ull fma2l(ull a, ull b, ull c) {
    ull d;
    asm("fma.rn.f32x2 %0,%1,%2,%3;" : "=l"(d) : "l"(a), "l"(b), "l"(c));
    return d;
}
__device__ __forceinline__ float tanhap(float x) {
    float y;
    asm("tanh.approx.f32 %0, %1;" : "=f"(y) : "f"(x));
    return y;
}

// ---------------- device-global precomputed constants ----------------
struct Consts {
    // scalar, pre-folded:
    // wr,wz (recurrent r/z) and wxr,wxz,br,bz carry the 0.5 sigmoid fold
    // wn,bnh carry a 0.5 fold so n_arg = nx + nh' + tr*nh'
    float wr[2][2], wz[2][2], wn[2][2];
    float wxr[2], wxz[2], wxn[2];
    float br[2], bz[2], bnx[2], bnh[2];
};
__device__ Consts g_c;
__device__ float2 g_poly[DEG + 1];   // monomial coeffs (alphaPoly, betaPoly), low->high

// ---------------- setup: parallel Chebyshev fit + weight folding --------------
__global__ void setup_kernel(const float* __restrict__ wih, const float* __restrict__ whh,
                             const float* __restrict__ bih, const float* __restrict__ bhh) {
    __shared__ double sA[DEG + 1], sB[DEG + 1];
    const int tid = threadIdx.x;
    const int NT = 128;
    const int N = 512;

    if (tid <= DEG) { sA[tid] = 0.0; sB[tid] = 0.0; }
    __syncthreads();

    // Each thread: 4 samples. cos(k*th) by Chebyshev recurrence (1 cos per sample).
    double la[DEG + 1], lb[DEG + 1];
    for (int k = 0; k <= DEG; k++) { la[k] = 0.0; lb[k] = 0.0; }
    for (int s = 0; s < N / NT; s++) {
        int j = tid + s * NT;
        double th = PI_D * (j + 0.5) / N;
        double ct = cos(th);
        double x = SFIT * ct;
        double t = tanh(x);
        double fa = 2.5 * exp(t);
        double fb = 4.0 / (1.0 + exp(-t));
        double ckm1 = 1.0, ck = ct;
        la[0] += fa; lb[0] += fb;
        la[1] += fa * ct; lb[1] += fb * ct;
        for (int k = 2; k <= DEG; k++) {
            double cn = 2.0 * ct * ck - ckm1;
            ckm1 = ck; ck = cn;
            la[k] += fa * cn; lb[k] += fb * cn;
        }
    }
    for (int k = 0; k <= DEG; k++) {
        atomicAdd(&sA[k], la[k] * (2.0 / N));
        atomicAdd(&sB[k], lb[k] * (2.0 / N));
    }
    __syncthreads();

    if (tid != 0) return;

    double cA[DEG + 1], cB[DEG + 1];
    for (int k = 0; k <= DEG; k++) { cA[k] = sA[k]; cB[k] = sB[k]; }
    cA[0] *= 0.5; cB[0] *= 0.5;

    // Chebyshev -> monomial in u, then u = x/SFIT rescale
    double mA[DEG + 1], mB[DEG + 1], tp[DEG + 1], tc[DEG + 1], tn[DEG + 1];
    for (int i = 0; i <= DEG; i++) { mA[i] = mB[i] = tp[i] = tc[i] = tn[i] = 0.0; }
    tp[0] = 1.0;
    tc[1] = 1.0;
    for (int i = 0; i <= DEG; i++) { mA[i] += cA[0] * tp[i]; mB[i] += cB[0] * tp[i]; }
    for (int i = 0; i <= DEG; i++) { mA[i] += cA[1] * tc[i]; mB[i] += cB[1] * tc[i]; }
    for (int k = 2; k <= DEG; k++) {
        for (int i = 0; i <= DEG; i++) tn[i] = -tp[i];
        for (int i = DEG; i >= 1; i--) tn[i] += 2.0 * tc[i - 1];
        for (int i = 0; i <= DEG; i++) {
            mA[i] += cA[k] * tn[i];
            mB[i] += cB[k] * tn[i];
            tp[i] = tc[i];
            tc[i] = tn[i];
        }
    }
    double sc = 1.0;
    for (int i = 0; i <= DEG; i++) {
        g_poly[i] = make_float2((float)(mA[i] / sc), (float)(mB[i] / sc));
        sc *= SFIT;
    }

    // weight folding: gate rows r=0,1 z=2,3 n=4,5 ; whh row-major (6x2)
    Consts c;
    for (int i = 0; i < 2; i++) {
        for (int k = 0; k < 2; k++) {
            c.wr[i][k] = 0.5f * whh[(0 + i) * 2 + k];
            c.wz[i][k] = 0.5f * whh[(2 + i) * 2 + k];
            c.wn[i][k] = 0.5f * whh[(4 + i) * 2 + k];
        }
        c.wxr[i] = 0.5f * wih[0 + i];
        c.wxz[i] = 0.5f * wih[2 + i];
        c.wxn[i] = wih[4 + i];
        c.br[i]  = 0.5f * (bih[0 + i] + bhh[0 + i]);
        c.bz[i]  = 0.5f * (bih[2 + i] + bhh[2 + i]);
        c.bnx[i] = bih[4 + i];
        c.bnh[i] = 0.5f * bhh[4 + i];
    }
    g_c = c;
}

// ---------------- main GRU scan: 1 thread = 1 batch row ----------------------
__global__ void __launch_bounds__(64, 1)
gru_kernel(const float* __restrict__ x, float* __restrict__ out) {
    const int b = blockIdx.x * 64 + threadIdx.x;

    const Consts c = g_c;
    ull P[DEG + 1];
#pragma unroll
    for (int i = 0; i <= DEG; i++) {
        float2 p = g_poly[i];
        P[i] = pk2(p.x, p.y);
    }

    const float* xr = x + (size_t)b * Tq;
    ulonglong2* orow = reinterpret_cast<ulonglong2*>(out + (size_t)b * Tq * 2);

    // 3-deep float4 prefetch ring
    float4 xc = *(const float4*)(xr);
    float4 x1 = *(const float4*)(xr + 4);
    float4 x2 = *(const float4*)(xr + 8);

    float h0 = 0.f, h1 = 0.f;

    for (int t0 = 0; t0 < Tq; t0 += 4) {
        int tpf = (t0 + 12 <= Tq - 4) ? (t0 + 12) : (Tq - 4);
        float4 xnext = *(const float4*)(xr + tpf);

        ull ob[4];
#pragma unroll
        for (int s = 0; s < 4; s++) {
            const float xt = (s == 0) ? xc.x : (s == 1) ? xc.y : (s == 2) ? xc.z : xc.w;

            // x-side pre-activations (off the h-chain)
            float axr0 = fmaf(xt, c.wxr[0], c.br[0]);
            float axr1 = fmaf(xt, c.wxr[1], c.br[1]);
            float axz0 = fmaf(xt, c.wxz[0], c.bz[0]);
            float axz1 = fmaf(xt, c.wxz[1], c.bz[1]);
            float nx0  = fmaf(xt, c.wxn[0], c.bnx[0]);
            float nx1  = fmaf(xt, c.wxn[1], c.bnx[1]);

            // gate pre-activations (scalar, straight into MUFU)
            float sr0 = fmaf(h0, c.wr[0][0], fmaf(h1, c.wr[0][1], axr0));
            float sr1 = fmaf(h0, c.wr[1][0], fmaf(h1, c.wr[1][1], axr1));
            float sz0 = fmaf(h0, c.wz[0][0], fmaf(h1, c.wz[0][1], axz0));
            float sz1 = fmaf(h0, c.wz[1][0], fmaf(h1, c.wz[1][1], axz1));
            float nh0 = fmaf(h0, c.wn[0][0], fmaf(h1, c.wn[0][1], c.bnh[0]));  // = 0.5*nh
            float nh1 = fmaf(h0, c.wn[1][0], fmaf(h1, c.wn[1][1], c.bnh[1]));

            float tr0 = tanhap(sr0), tr1 = tanhap(sr1);
            float tz0 = tanhap(sz0), tz1 = tanhap(sz1);

            // n = tanh(nx + r*nh) with r = 0.5*tr+0.5 -> nx + nh' + tr*nh'
            float p0 = nx0 + nh0;
            float p1 = nx1 + nh1;
            float na0 = fmaf(tr0, nh0, p0);
            float na1 = fmaf(tr1, nh1, p1);
            float n0 = tanhap(na0), n1 = tanhap(na1);

            // h_new = z*(h-n) + n,  z = 0.5*tz+0.5
            float z0 = fmaf(tz0, 0.5f, 0.5f);
            float z1 = fmaf(tz1, 0.5f, 0.5f);
            float d0 = h0 - n0;
            float d1 = h1 - n1;
            h0 = fmaf(z0, d0, n0);
            h1 = fmaf(z1, d1, n1);

            // outputs: packed Horner, lane.lo -> alphaPoly(h0), lane.hi -> betaPoly(h1)
            ull hh = pk2(h0, h1);
            ull acc = P[DEG];
#pragma unroll
            for (int k = DEG - 1; k >= 0; k--) acc = fma2l(acc, hh, P[k]);
            ob[s] = acc;
        }

        orow[(t0 >> 1) + 0] = make_ulonglong2(ob[0], ob[1]);
        orow[(t0 >> 1) + 1] = make_ulonglong2(ob[2], ob[3]);

        xc = x1; x1 = x2; x2 = xnext;
    }
}

extern "C" void kernel_launch(void* const* d_in, const int* in_sizes, int n_in,
                              void* d_out, int out_size) {
    const float* x   = (const float*)d_in[0];
    const float* wih = (const float*)d_in[1];
    const float* whh = (const float*)d_in[2];
    const float* bih = (const float*)d_in[3];
    const float* bhh = (const float*)d_in[4];

    setup_kernel<<<1, 128>>>(wih, whh, bih, bhh);
    gru_kernel<<<128, 64>>>(x, (float*)d_out);
}